// round 14
// baseline (speedup 1.0000x reference)
#include <cuda_runtime.h>

#define W 4096
#define S 4096
#define NK 1024
#define SHARP 10.0f
#define ATT_EPS 1e-8f     // keys below this attention contribute <1e-5 rel -> drop
#define KEEP_ROWS 3072    // last 3072 holo rows (96MB) left evict-normal in L2

// ---- scratch (device globals; no allocations allowed) ----
__device__ __align__(16) float g_mix_re[W];
__device__ __align__(16) float g_mix_im[W];
__device__ float g_corr[NK];
__device__ int   g_cidx[NK];   // compacted key indices with att > ATT_EPS
__device__ float g_catt[NK];   // their attention weights
__device__ int   g_cnt;        // number of compacted entries
__device__ int   g_done;       // completion counter for k_corr tail block (init 0)

// ---------------------------------------------------------------------------
// Stage 1: noisy_mix[w] = sum_s holo[w,s] * conj(cue[w,s])
//   re = hr*cr + hi*ci ; im = hi*cr - hr*ci
// Block-per-row, dual accumulator pairs, unroll 8 (verified 6.46 TB/s).
// holo rows >= W-KEEP_ROWS evict-normal; rest streaming.
// ---------------------------------------------------------------------------
__global__ void __launch_bounds__(256) k_mix(
        const float4* __restrict__ hr, const float4* __restrict__ hi,
        const float4* __restrict__ cr, const float4* __restrict__ ci) {
    const int w = blockIdx.x;
    if (w == 0 && threadIdx.x == 0) g_done = 0;
    const size_t base = (size_t)w * (S / 4) + threadIdx.x;
    float re0 = 0.f, im0 = 0.f, re1 = 0.f, im1 = 0.f;
    if (w >= W - KEEP_ROWS) {
        #pragma unroll 8
        for (int it = 0; it < (S / 4) / 256; it++) {
            const size_t idx = base + (size_t)it * 256;
            float4 a = hr[idx];
            float4 b = hi[idx];
            float4 c = __ldcs(cr + idx);
            float4 d = __ldcs(ci + idx);
            re0 += a.x * c.x + b.x * d.x;  im0 += b.x * c.x - a.x * d.x;
            re1 += a.y * c.y + b.y * d.y;  im1 += b.y * c.y - a.y * d.y;
            re0 += a.z * c.z + b.z * d.z;  im0 += b.z * c.z - a.z * d.z;
            re1 += a.w * c.w + b.w * d.w;  im1 += b.w * c.w - a.w * d.w;
        }
    } else {
        #pragma unroll 8
        for (int it = 0; it < (S / 4) / 256; it++) {
            const size_t idx = base + (size_t)it * 256;
            float4 a = __ldcs(hr + idx);
            float4 b = __ldcs(hi + idx);
            float4 c = __ldcs(cr + idx);
            float4 d = __ldcs(ci + idx);
            re0 += a.x * c.x + b.x * d.x;  im0 += b.x * c.x - a.x * d.x;
            re1 += a.y * c.y + b.y * d.y;  im1 += b.y * c.y - a.y * d.y;
            re0 += a.z * c.z + b.z * d.z;  im0 += b.z * c.z - a.z * d.z;
            re1 += a.w * c.w + b.w * d.w;  im1 += b.w * c.w - a.w * d.w;
        }
    }
    float are = re0 + re1, aim = im0 + im1;
    __shared__ float s1[8], s2[8];
    #pragma unroll
    for (int o = 16; o > 0; o >>= 1) {
        are += __shfl_down_sync(0xffffffffu, are, o);
        aim += __shfl_down_sync(0xffffffffu, aim, o);
    }
    const int lane = threadIdx.x & 31, wid = threadIdx.x >> 5;
    if (lane == 0) { s1[wid] = are; s2[wid] = aim; }
    __syncthreads();
    if (wid == 0) {
        are = (lane < 8) ? s1[lane] : 0.f;
        aim = (lane < 8) ? s2[lane] : 0.f;
        #pragma unroll
        for (int o = 4; o > 0; o >>= 1) {
            are += __shfl_down_sync(0xffffffffu, are, o);
            aim += __shfl_down_sync(0xffffffffu, aim, o);
        }
        if (lane == 0) { g_mix_re[w] = are; g_mix_im[w] = aim; }
    }
}

// ---------------------------------------------------------------------------
// Stage 2+3 fused: corr[n] = | keys[n,:] . mix |, then the LAST block to
// finish runs softmax(corr*SHARP) + deterministic compaction.
// Dual accumulator pairs to halve the FMA RAW chain.
// ---------------------------------------------------------------------------
__global__ void __launch_bounds__(256) k_corr(
        const float4* __restrict__ kr, const float4* __restrict__ ki) {
    const int n = blockIdx.x;
    const size_t base = (size_t)n * (W / 4) + threadIdx.x;
    const float4* __restrict__ mr = (const float4*)g_mix_re;
    const float4* __restrict__ mi = (const float4*)g_mix_im;
    float ar0 = 0.f, ai0 = 0.f, ar1 = 0.f, ai1 = 0.f;
    #pragma unroll 4
    for (int it = 0; it < (W / 4) / 256; it++) {
        const int i = threadIdx.x + it * 256;
        float4 a = __ldcs(kr + base + (size_t)it * 256);
        float4 b = __ldcs(ki + base + (size_t)it * 256);
        float4 c = mr[i];
        float4 d = mi[i];
        ar0 += a.x * c.x - b.x * d.x;  ai0 += a.x * d.x + b.x * c.x;
        ar1 += a.y * c.y - b.y * d.y;  ai1 += a.y * d.y + b.y * c.y;
        ar0 += a.z * c.z - b.z * d.z;  ai0 += a.z * d.z + b.z * c.z;
        ar1 += a.w * c.w - b.w * d.w;  ai1 += a.w * d.w + b.w * c.w;
    }
    float ar = ar0 + ar1, ai = ai0 + ai1;
    __shared__ float s1[8], s2[8];
    #pragma unroll
    for (int o = 16; o > 0; o >>= 1) {
        ar += __shfl_down_sync(0xffffffffu, ar, o);
        ai += __shfl_down_sync(0xffffffffu, ai, o);
    }
    const int lane = threadIdx.x & 31, wid = threadIdx.x >> 5;
    if (lane == 0) { s1[wid] = ar; s2[wid] = ai; }
    __syncthreads();
    __shared__ bool s_last;
    if (threadIdx.x == 0) {
        float arr = 0.f, aii = 0.f;
        #pragma unroll
        for (int k = 0; k < 8; k++) { arr += s1[k]; aii += s2[k]; }
        g_corr[n] = sqrtf(arr * arr + aii * aii);
        __threadfence();
        const int prev = atomicAdd(&g_done, 1);
        s_last = (prev == NK - 1);
    }
    __syncthreads();
    if (!s_last) return;

    // ---- tail block: softmax + deterministic compaction (256 thr x 4 ea) ----
    __threadfence();
    const int t = threadIdx.x;
    float v[4];
    #pragma unroll
    for (int j = 0; j < 4; j++) v[j] = g_corr[t * 4 + j] * SHARP;

    __shared__ float swarp[8];
    float m = fmaxf(fmaxf(v[0], v[1]), fmaxf(v[2], v[3]));
    #pragma unroll
    for (int o = 16; o > 0; o >>= 1) m = fmaxf(m, __shfl_xor_sync(0xffffffffu, m, o));
    if (lane == 0) swarp[wid] = m;
    __syncthreads();
    m = swarp[0];
    #pragma unroll
    for (int k = 1; k < 8; k++) m = fmaxf(m, swarp[k]);

    float e[4];
    float sm = 0.f;
    #pragma unroll
    for (int j = 0; j < 4; j++) { e[j] = expf(v[j] - m); sm += e[j]; }
    #pragma unroll
    for (int o = 16; o > 0; o >>= 1) sm += __shfl_xor_sync(0xffffffffu, sm, o);
    __syncthreads();
    if (lane == 0) swarp[wid] = sm;
    __syncthreads();
    sm = swarp[0];
    #pragma unroll
    for (int k = 1; k < 8; k++) sm += swarp[k];
    const float inv = 1.0f / sm;

    float att[4];
    int flg[4], cntloc = 0;
    #pragma unroll
    for (int j = 0; j < 4; j++) {
        att[j] = e[j] * inv;
        flg[j] = (att[j] > ATT_EPS) ? 1 : 0;
        cntloc += flg[j];
    }
    int sc = cntloc;
    #pragma unroll
    for (int o = 1; o < 32; o <<= 1) {
        int u = __shfl_up_sync(0xffffffffu, sc, o);
        if (lane >= o) sc += u;
    }
    __shared__ int swsum[8];
    if (lane == 31) swsum[wid] = sc;
    int excl = sc - cntloc;
    __syncthreads();
    int woff = 0;
    #pragma unroll
    for (int k = 0; k < 8; k++) if (k < wid) woff += swsum[k];
    int pos = woff + excl;
    #pragma unroll
    for (int j = 0; j < 4; j++) {
        if (flg[j]) {
            g_cidx[pos] = t * 4 + j;
            g_catt[pos] = att[j];
            pos++;
        }
    }
    if (t == 255) g_cnt = pos;
    if (t == 0) g_done = 0;   // reset for next graph replay
}

// ---------------------------------------------------------------------------
// Stage 4+5 fused: per row w, clean_key[w] = sum_j catt[j]*keys[cidx[j], w],
// then out[0] = hr*ckr - hi*cki ; out[1] = hr*cki + hi*ckr.
// Reverse row order; unroll 8 for deeper load/store pipelining.
// ---------------------------------------------------------------------------
__global__ void __launch_bounds__(256) k_out(
        const float4* __restrict__ hr, const float4* __restrict__ hi,
        const float* __restrict__ kr, const float* __restrict__ ki,
        float4* __restrict__ out) {
    const int w = (W - 1) - blockIdx.x;   // reverse row order
    const int cnt = g_cnt;
    float ckr = 0.f, cki = 0.f;
    for (int j = 0; j < cnt; j++) {
        const float a = g_catt[j];
        const size_t off = (size_t)g_cidx[j] * W + w;
        ckr = fmaf(a, __ldg(kr + off), ckr);
        cki = fmaf(a, __ldg(ki + off), cki);
    }
    const size_t base = (size_t)w * (S / 4) + threadIdx.x;
    #pragma unroll 8
    for (int it = 0; it < (S / 4) / 256; it++) {
        const size_t i = base + (size_t)it * 256;
        const float4 a = __ldcs(hr + i);
        const float4 b = __ldcs(hi + i);
        float4 o0, o1;
        o0.x = a.x * ckr - b.x * cki;  o1.x = fmaf(a.x, cki, b.x * ckr);
        o0.y = a.y * ckr - b.y * cki;  o1.y = fmaf(a.y, cki, b.y * ckr);
        o0.z = a.z * ckr - b.z * cki;  o1.z = fmaf(a.z, cki, b.z * ckr);
        o0.w = a.w * ckr - b.w * cki;  o1.w = fmaf(a.w, cki, b.w * ckr);
        __stcs(out + i, o0);
        __stcs(out + i + (size_t)W * (S / 4), o1);
    }
}

extern "C" void kernel_launch(void* const* d_in, const int* in_sizes, int n_in,
                              void* d_out, int out_size) {
    const float* holo_re = (const float*)d_in[0];
    const float* holo_im = (const float*)d_in[1];
    const float* cue_re  = (const float*)d_in[2];
    const float* cue_im  = (const float*)d_in[3];
    const float* keys_re = (const float*)d_in[4];
    const float* keys_im = (const float*)d_in[5];
    float* out = (float*)d_out;

    k_mix<<<W, 256>>>((const float4*)holo_re, (const float4*)holo_im,
                      (const float4*)cue_re, (const float4*)cue_im);
    k_corr<<<NK, 256>>>((const float4*)keys_re, (const float4*)keys_im);
    k_out<<<W, 256>>>((const float4*)holo_re, (const float4*)holo_im,
                      keys_re, keys_im, (float4*)out);
}

// round 15
// speedup vs baseline: 1.0224x; 1.0224x over previous
#include <cuda_runtime.h>

#define W 4096
#define S 4096
#define NK 1024
#define SHARP 10.0f
#define ATT_EPS 1e-8f     // keys below this attention contribute <1e-5 rel -> drop
#define KEEP_ROWS 3072    // last 3072 holo rows (96MB) left evict-normal in L2

// ---- scratch (device globals; no allocations allowed) ----
__device__ __align__(16) float g_mix_re[W];
__device__ __align__(16) float g_mix_im[W];
__device__ float g_corr[NK];
__device__ int   g_cidx[NK];   // compacted key indices with att > ATT_EPS
__device__ float g_catt[NK];   // their attention weights
__device__ int   g_cnt;        // number of compacted entries
__device__ int   g_done;       // completion counter for k_corr tail block (init 0)

// ---------------------------------------------------------------------------
// Stage 1: noisy_mix[w] = sum_s holo[w,s] * conj(cue[w,s])
//   re = hr*cr + hi*ci ; im = hi*cr - hr*ci
// Block-per-row (measured-best structure). TWO independent accumulator pairs
// halve the FMA RAW chain so warps drain loads faster (6.46 TB/s measured).
// holo rows >= W-KEEP_ROWS evict-normal; rest streaming.
// ---------------------------------------------------------------------------
__global__ void __launch_bounds__(256) k_mix(
        const float4* __restrict__ hr, const float4* __restrict__ hi,
        const float4* __restrict__ cr, const float4* __restrict__ ci) {
    const int w = blockIdx.x;
    if (w == 0 && threadIdx.x == 0) g_done = 0;
    const size_t base = (size_t)w * (S / 4) + threadIdx.x;
    float re0 = 0.f, im0 = 0.f, re1 = 0.f, im1 = 0.f;
    if (w >= W - KEEP_ROWS) {
        #pragma unroll 8
        for (int it = 0; it < (S / 4) / 256; it++) {
            const size_t idx = base + (size_t)it * 256;
            float4 a = hr[idx];
            float4 b = hi[idx];
            float4 c = __ldcs(cr + idx);
            float4 d = __ldcs(ci + idx);
            re0 += a.x * c.x + b.x * d.x;  im0 += b.x * c.x - a.x * d.x;
            re1 += a.y * c.y + b.y * d.y;  im1 += b.y * c.y - a.y * d.y;
            re0 += a.z * c.z + b.z * d.z;  im0 += b.z * c.z - a.z * d.z;
            re1 += a.w * c.w + b.w * d.w;  im1 += b.w * c.w - a.w * d.w;
        }
    } else {
        #pragma unroll 8
        for (int it = 0; it < (S / 4) / 256; it++) {
            const size_t idx = base + (size_t)it * 256;
            float4 a = __ldcs(hr + idx);
            float4 b = __ldcs(hi + idx);
            float4 c = __ldcs(cr + idx);
            float4 d = __ldcs(ci + idx);
            re0 += a.x * c.x + b.x * d.x;  im0 += b.x * c.x - a.x * d.x;
            re1 += a.y * c.y + b.y * d.y;  im1 += b.y * c.y - a.y * d.y;
            re0 += a.z * c.z + b.z * d.z;  im0 += b.z * c.z - a.z * d.z;
            re1 += a.w * c.w + b.w * d.w;  im1 += b.w * c.w - a.w * d.w;
        }
    }
    float are = re0 + re1, aim = im0 + im1;
    __shared__ float s1[8], s2[8];
    #pragma unroll
    for (int o = 16; o > 0; o >>= 1) {
        are += __shfl_down_sync(0xffffffffu, are, o);
        aim += __shfl_down_sync(0xffffffffu, aim, o);
    }
    const int lane = threadIdx.x & 31, wid = threadIdx.x >> 5;
    if (lane == 0) { s1[wid] = are; s2[wid] = aim; }
    __syncthreads();
    if (wid == 0) {
        are = (lane < 8) ? s1[lane] : 0.f;
        aim = (lane < 8) ? s2[lane] : 0.f;
        #pragma unroll
        for (int o = 4; o > 0; o >>= 1) {
            are += __shfl_down_sync(0xffffffffu, are, o);
            aim += __shfl_down_sync(0xffffffffu, aim, o);
        }
        if (lane == 0) { g_mix_re[w] = are; g_mix_im[w] = aim; }
    }
}

// ---------------------------------------------------------------------------
// Stage 2+3 fused: corr[n] = | keys[n,:] . mix |, then the LAST block to
// finish runs softmax(corr*SHARP) + deterministic compaction.
// keys via __ldcs so the 32MB stream doesn't evict the resident holo set.
// ---------------------------------------------------------------------------
__global__ void __launch_bounds__(256) k_corr(
        const float4* __restrict__ kr, const float4* __restrict__ ki) {
    const int n = blockIdx.x;
    const size_t base = (size_t)n * (W / 4) + threadIdx.x;
    const float4* __restrict__ mr = (const float4*)g_mix_re;
    const float4* __restrict__ mi = (const float4*)g_mix_im;
    float ar = 0.f, ai = 0.f;
    #pragma unroll 4
    for (int it = 0; it < (W / 4) / 256; it++) {
        const int i = threadIdx.x + it * 256;
        float4 a = __ldcs(kr + base + (size_t)it * 256);
        float4 b = __ldcs(ki + base + (size_t)it * 256);
        float4 c = mr[i];
        float4 d = mi[i];
        ar += a.x * c.x - b.x * d.x;  ai += a.x * d.x + b.x * c.x;
        ar += a.y * c.y - b.y * d.y;  ai += a.y * d.y + b.y * c.y;
        ar += a.z * c.z - b.z * d.z;  ai += a.z * d.z + b.z * c.z;
        ar += a.w * c.w - b.w * d.w;  ai += a.w * d.w + b.w * c.w;
    }
    __shared__ float s1[8], s2[8];
    #pragma unroll
    for (int o = 16; o > 0; o >>= 1) {
        ar += __shfl_down_sync(0xffffffffu, ar, o);
        ai += __shfl_down_sync(0xffffffffu, ai, o);
    }
    const int lane = threadIdx.x & 31, wid = threadIdx.x >> 5;
    if (lane == 0) { s1[wid] = ar; s2[wid] = ai; }
    __syncthreads();
    __shared__ bool s_last;
    if (threadIdx.x == 0) {
        float arr = 0.f, aii = 0.f;
        #pragma unroll
        for (int k = 0; k < 8; k++) { arr += s1[k]; aii += s2[k]; }
        g_corr[n] = sqrtf(arr * arr + aii * aii);
        __threadfence();
        const int prev = atomicAdd(&g_done, 1);
        s_last = (prev == NK - 1);
    }
    __syncthreads();
    if (!s_last) return;

    // ---- tail block: softmax + deterministic compaction (256 thr x 4 ea) ----
    __threadfence();
    const int t = threadIdx.x;
    float v[4];
    #pragma unroll
    for (int j = 0; j < 4; j++) v[j] = g_corr[t * 4 + j] * SHARP;

    __shared__ float swarp[8];
    float m = fmaxf(fmaxf(v[0], v[1]), fmaxf(v[2], v[3]));
    #pragma unroll
    for (int o = 16; o > 0; o >>= 1) m = fmaxf(m, __shfl_xor_sync(0xffffffffu, m, o));
    if (lane == 0) swarp[wid] = m;
    __syncthreads();
    m = swarp[0];
    #pragma unroll
    for (int k = 1; k < 8; k++) m = fmaxf(m, swarp[k]);

    float e[4];
    float sm = 0.f;
    #pragma unroll
    for (int j = 0; j < 4; j++) { e[j] = expf(v[j] - m); sm += e[j]; }
    #pragma unroll
    for (int o = 16; o > 0; o >>= 1) sm += __shfl_xor_sync(0xffffffffu, sm, o);
    __syncthreads();
    if (lane == 0) swarp[wid] = sm;
    __syncthreads();
    sm = swarp[0];
    #pragma unroll
    for (int k = 1; k < 8; k++) sm += swarp[k];
    const float inv = 1.0f / sm;

    float att[4];
    int flg[4], cntloc = 0;
    #pragma unroll
    for (int j = 0; j < 4; j++) {
        att[j] = e[j] * inv;
        flg[j] = (att[j] > ATT_EPS) ? 1 : 0;
        cntloc += flg[j];
    }
    int sc = cntloc;
    #pragma unroll
    for (int o = 1; o < 32; o <<= 1) {
        int u = __shfl_up_sync(0xffffffffu, sc, o);
        if (lane >= o) sc += u;
    }
    __shared__ int swsum[8];
    if (lane == 31) swsum[wid] = sc;
    int excl = sc - cntloc;
    __syncthreads();
    int woff = 0;
    #pragma unroll
    for (int k = 0; k < 8; k++) if (k < wid) woff += swsum[k];
    int pos = woff + excl;
    #pragma unroll
    for (int j = 0; j < 4; j++) {
        if (flg[j]) {
            g_cidx[pos] = t * 4 + j;
            g_catt[pos] = att[j];
            pos++;
        }
    }
    if (t == 255) g_cnt = pos;
    if (t == 0) g_done = 0;   // reset for next graph replay
}

// ---------------------------------------------------------------------------
// Stage 4+5 fused: per row w, clean_key[w] = sum_j catt[j]*keys[cidx[j], w],
// then out[0] = hr*ckr - hi*cki ; out[1] = hr*cki + hi*ckr.
// Reverse row order: first rows read are the L2-resident holo rows.
// ---------------------------------------------------------------------------
__global__ void __launch_bounds__(256) k_out(
        const float4* __restrict__ hr, const float4* __restrict__ hi,
        const float* __restrict__ kr, const float* __restrict__ ki,
        float4* __restrict__ out) {
    const int w = (W - 1) - blockIdx.x;   // reverse row order
    const int cnt = g_cnt;
    float ckr = 0.f, cki = 0.f;
    for (int j = 0; j < cnt; j++) {
        const float a = g_catt[j];
        const size_t off = (size_t)g_cidx[j] * W + w;
        ckr = fmaf(a, __ldg(kr + off), ckr);
        cki = fmaf(a, __ldg(ki + off), cki);
    }
    const size_t base = (size_t)w * (S / 4) + threadIdx.x;
    #pragma unroll 4
    for (int it = 0; it < (S / 4) / 256; it++) {
        const size_t i = base + (size_t)it * 256;
        const float4 a = __ldcs(hr + i);
        const float4 b = __ldcs(hi + i);
        float4 o0, o1;
        o0.x = a.x * ckr - b.x * cki;  o1.x = fmaf(a.x, cki, b.x * ckr);
        o0.y = a.y * ckr - b.y * cki;  o1.y = fmaf(a.y, cki, b.y * ckr);
        o0.z = a.z * ckr - b.z * cki;  o1.z = fmaf(a.z, cki, b.z * ckr);
        o0.w = a.w * ckr - b.w * cki;  o1.w = fmaf(a.w, cki, b.w * ckr);
        __stcs(out + i, o0);
        __stcs(out + i + (size_t)W * (S / 4), o1);
    }
}

extern "C" void kernel_launch(void* const* d_in, const int* in_sizes, int n_in,
                              void* d_out, int out_size) {
    const float* holo_re = (const float*)d_in[0];
    const float* holo_im = (const float*)d_in[1];
    const float* cue_re  = (const float*)d_in[2];
    const float* cue_im  = (const float*)d_in[3];
    const float* keys_re = (const float*)d_in[4];
    const float* keys_im = (const float*)d_in[5];
    float* out = (float*)d_out;

    k_mix<<<W, 256>>>((const float4*)holo_re, (const float4*)holo_im,
                      (const float4*)cue_re, (const float4*)cue_im);
    k_corr<<<NK, 256>>>((const float4*)keys_re, (const float4*)keys_im);
    k_out<<<W, 256>>>((const float4*)holo_re, (const float4*)holo_im,
                      keys_re, keys_im, (float4*)out);
}

// round 16
// speedup vs baseline: 1.0361x; 1.0134x over previous
#include <cuda_runtime.h>

#define W 4096
#define S 4096
#define NK 1024
#define SHARP 10.0f
#define ATT_EPS 1e-8f     // keys below this attention contribute <1e-5 rel -> drop
#define KEEP_ROWS 3072    // last 3072 holo rows (96MB) left evict-normal in L2

// ---- scratch (device globals; no allocations allowed) ----
__device__ __align__(16) float g_mix_re[W];
__device__ __align__(16) float g_mix_im[W];
__device__ float g_corr[NK];
__device__ int   g_cidx[NK];   // compacted key indices with att > ATT_EPS
__device__ float g_catt[NK];   // their attention weights
__device__ int   g_cnt;        // number of compacted entries
__device__ int   g_done;       // completion counter for k_corr tail block (init 0)

// ---------------------------------------------------------------------------
// Stage 1: noisy_mix[w] = sum_s holo[w,s] * conj(cue[w,s])
// Block-per-row, dual accumulator pairs (verified 6.46 TB/s).
// Fires the PDL trigger immediately: k_corr may launch and run its
// INDEPENDENT preamble (keys prefetch) while k_mix streams.
// ---------------------------------------------------------------------------
__global__ void __launch_bounds__(256) k_mix(
        const float4* __restrict__ hr, const float4* __restrict__ hi,
        const float4* __restrict__ cr, const float4* __restrict__ ci) {
    cudaTriggerProgrammaticLaunchCompletion();
    const int w = blockIdx.x;
    if (w == 0 && threadIdx.x == 0) g_done = 0;
    const size_t base = (size_t)w * (S / 4) + threadIdx.x;
    float re0 = 0.f, im0 = 0.f, re1 = 0.f, im1 = 0.f;
    if (w >= W - KEEP_ROWS) {
        #pragma unroll
        for (int it = 0; it < (S / 4) / 256; it++) {
            const size_t idx = base + (size_t)it * 256;
            float4 a = hr[idx];
            float4 b = hi[idx];
            float4 c = __ldcs(cr + idx);
            float4 d = __ldcs(ci + idx);
            re0 += a.x * c.x + b.x * d.x;  im0 += b.x * c.x - a.x * d.x;
            re1 += a.y * c.y + b.y * d.y;  im1 += b.y * c.y - a.y * d.y;
            re0 += a.z * c.z + b.z * d.z;  im0 += b.z * c.z - a.z * d.z;
            re1 += a.w * c.w + b.w * d.w;  im1 += b.w * c.w - a.w * d.w;
        }
    } else {
        #pragma unroll
        for (int it = 0; it < (S / 4) / 256; it++) {
            const size_t idx = base + (size_t)it * 256;
            float4 a = __ldcs(hr + idx);
            float4 b = __ldcs(hi + idx);
            float4 c = __ldcs(cr + idx);
            float4 d = __ldcs(ci + idx);
            re0 += a.x * c.x + b.x * d.x;  im0 += b.x * c.x - a.x * d.x;
            re1 += a.y * c.y + b.y * d.y;  im1 += b.y * c.y - a.y * d.y;
            re0 += a.z * c.z + b.z * d.z;  im0 += b.z * c.z - a.z * d.z;
            re1 += a.w * c.w + b.w * d.w;  im1 += b.w * c.w - a.w * d.w;
        }
    }
    float are = re0 + re1, aim = im0 + im1;
    __shared__ float s1[8], s2[8];
    #pragma unroll
    for (int o = 16; o > 0; o >>= 1) {
        are += __shfl_down_sync(0xffffffffu, are, o);
        aim += __shfl_down_sync(0xffffffffu, aim, o);
    }
    const int lane = threadIdx.x & 31, wid = threadIdx.x >> 5;
    if (lane == 0) { s1[wid] = are; s2[wid] = aim; }
    __syncthreads();
    if (wid == 0) {
        are = (lane < 8) ? s1[lane] : 0.f;
        aim = (lane < 8) ? s2[lane] : 0.f;
        #pragma unroll
        for (int o = 4; o > 0; o >>= 1) {
            are += __shfl_down_sync(0xffffffffu, are, o);
            aim += __shfl_down_sync(0xffffffffu, aim, o);
        }
        if (lane == 0) { g_mix_re[w] = are; g_mix_im[w] = aim; }
    }
}

// ---------------------------------------------------------------------------
// Stage 2+3 fused, PDL-dependent on k_mix: the keys prefetch (independent of
// k_mix's output) runs BEFORE the grid-dependency sync, overlapping k_mix's
// tail. Then corr, and the LAST block runs softmax + compaction.
// ---------------------------------------------------------------------------
__global__ void __launch_bounds__(256) k_corr(
        const float4* __restrict__ kr, const float4* __restrict__ ki) {
    const int n = blockIdx.x;
    const size_t base = (size_t)n * (W / 4) + threadIdx.x;

    // --- independent preamble: prefetch this block's key row into registers ---
    float4 ka[4], kb[4];
    #pragma unroll
    for (int it = 0; it < 4; it++) {
        ka[it] = __ldcs(kr + base + (size_t)it * 256);
        kb[it] = __ldcs(ki + base + (size_t)it * 256);
    }

    cudaGridDependencySynchronize();   // wait for k_mix grid completion
    cudaTriggerProgrammaticLaunchCompletion();  // let k_out launch early

    const float4* __restrict__ mr = (const float4*)g_mix_re;
    const float4* __restrict__ mi = (const float4*)g_mix_im;
    float ar = 0.f, ai = 0.f;
    #pragma unroll
    for (int it = 0; it < 4; it++) {
        const int i = threadIdx.x + it * 256;
        float4 a = ka[it];
        float4 b = kb[it];
        float4 c = mr[i];
        float4 d = mi[i];
        ar += a.x * c.x - b.x * d.x;  ai += a.x * d.x + b.x * c.x;
        ar += a.y * c.y - b.y * d.y;  ai += a.y * d.y + b.y * c.y;
        ar += a.z * c.z - b.z * d.z;  ai += a.z * d.z + b.z * c.z;
        ar += a.w * c.w - b.w * d.w;  ai += a.w * d.w + b.w * c.w;
    }
    __shared__ float s1[8], s2[8];
    #pragma unroll
    for (int o = 16; o > 0; o >>= 1) {
        ar += __shfl_down_sync(0xffffffffu, ar, o);
        ai += __shfl_down_sync(0xffffffffu, ai, o);
    }
    const int lane = threadIdx.x & 31, wid = threadIdx.x >> 5;
    if (lane == 0) { s1[wid] = ar; s2[wid] = ai; }
    __syncthreads();
    __shared__ bool s_last;
    if (threadIdx.x == 0) {
        float arr = 0.f, aii = 0.f;
        #pragma unroll
        for (int k = 0; k < 8; k++) { arr += s1[k]; aii += s2[k]; }
        g_corr[n] = sqrtf(arr * arr + aii * aii);
        __threadfence();
        const int prev = atomicAdd(&g_done, 1);
        s_last = (prev == NK - 1);
    }
    __syncthreads();
    if (!s_last) return;

    // ---- tail block: softmax + deterministic compaction (256 thr x 4 ea) ----
    __threadfence();
    const int t = threadIdx.x;
    float v[4];
    #pragma unroll
    for (int j = 0; j < 4; j++) v[j] = g_corr[t * 4 + j] * SHARP;

    __shared__ float swarp[8];
    float m = fmaxf(fmaxf(v[0], v[1]), fmaxf(v[2], v[3]));
    #pragma unroll
    for (int o = 16; o > 0; o >>= 1) m = fmaxf(m, __shfl_xor_sync(0xffffffffu, m, o));
    if (lane == 0) swarp[wid] = m;
    __syncthreads();
    m = swarp[0];
    #pragma unroll
    for (int k = 1; k < 8; k++) m = fmaxf(m, swarp[k]);

    float e[4];
    float sm = 0.f;
    #pragma unroll
    for (int j = 0; j < 4; j++) { e[j] = expf(v[j] - m); sm += e[j]; }
    #pragma unroll
    for (int o = 16; o > 0; o >>= 1) sm += __shfl_xor_sync(0xffffffffu, sm, o);
    __syncthreads();
    if (lane == 0) swarp[wid] = sm;
    __syncthreads();
    sm = swarp[0];
    #pragma unroll
    for (int k = 1; k < 8; k++) sm += swarp[k];
    const float inv = 1.0f / sm;

    float att[4];
    int flg[4], cntloc = 0;
    #pragma unroll
    for (int j = 0; j < 4; j++) {
        att[j] = e[j] * inv;
        flg[j] = (att[j] > ATT_EPS) ? 1 : 0;
        cntloc += flg[j];
    }
    int sc = cntloc;
    #pragma unroll
    for (int o = 1; o < 32; o <<= 1) {
        int u = __shfl_up_sync(0xffffffffu, sc, o);
        if (lane >= o) sc += u;
    }
    __shared__ int swsum[8];
    if (lane == 31) swsum[wid] = sc;
    int excl = sc - cntloc;
    __syncthreads();
    int woff = 0;
    #pragma unroll
    for (int k = 0; k < 8; k++) if (k < wid) woff += swsum[k];
    int pos = woff + excl;
    #pragma unroll
    for (int j = 0; j < 4; j++) {
        if (flg[j]) {
            g_cidx[pos] = t * 4 + j;
            g_catt[pos] = att[j];
            pos++;
        }
    }
    if (t == 255) g_cnt = pos;
    if (t == 0) g_done = 0;   // reset for next graph replay
}

// ---------------------------------------------------------------------------
// Stage 4+5 fused, PDL-dependent on k_corr: the first half of the holo row
// (independent of k_corr) is prefetched BEFORE the dependency sync, hiding
// k_corr's tail/softmax latency under DRAM reads. Reverse row order keeps the
// L2-resident holo rows first.
// ---------------------------------------------------------------------------
__global__ void __launch_bounds__(256) k_out(
        const float4* __restrict__ hr, const float4* __restrict__ hi,
        const float* __restrict__ kr, const float* __restrict__ ki,
        float4* __restrict__ out) {
    const int w = (W - 1) - blockIdx.x;   // reverse row order
    const size_t base = (size_t)w * (S / 4) + threadIdx.x;

    // --- independent preamble: prefetch first 2 of 4 row chunks ---
    float4 pa[2], pb[2];
    #pragma unroll
    for (int it = 0; it < 2; it++) {
        pa[it] = __ldcs(hr + base + (size_t)it * 256);
        pb[it] = __ldcs(hi + base + (size_t)it * 256);
    }

    cudaGridDependencySynchronize();   // wait for k_corr grid completion

    const int cnt = g_cnt;
    float ckr = 0.f, cki = 0.f;
    for (int j = 0; j < cnt; j++) {
        const float a = g_catt[j];
        const size_t off = (size_t)g_cidx[j] * W + w;
        ckr = fmaf(a, __ldg(kr + off), ckr);
        cki = fmaf(a, __ldg(ki + off), cki);
    }

    // buffered chunks
    #pragma unroll
    for (int it = 0; it < 2; it++) {
        const size_t i = base + (size_t)it * 256;
        const float4 a = pa[it];
        const float4 b = pb[it];
        float4 o0, o1;
        o0.x = a.x * ckr - b.x * cki;  o1.x = fmaf(a.x, cki, b.x * ckr);
        o0.y = a.y * ckr - b.y * cki;  o1.y = fmaf(a.y, cki, b.y * ckr);
        o0.z = a.z * ckr - b.z * cki;  o1.z = fmaf(a.z, cki, b.z * ckr);
        o0.w = a.w * ckr - b.w * cki;  o1.w = fmaf(a.w, cki, b.w * ckr);
        __stcs(out + i, o0);
        __stcs(out + i + (size_t)W * (S / 4), o1);
    }
    // remaining chunks
    #pragma unroll
    for (int it = 2; it < (S / 4) / 256; it++) {
        const size_t i = base + (size_t)it * 256;
        const float4 a = __ldcs(hr + i);
        const float4 b = __ldcs(hi + i);
        float4 o0, o1;
        o0.x = a.x * ckr - b.x * cki;  o1.x = fmaf(a.x, cki, b.x * ckr);
        o0.y = a.y * ckr - b.y * cki;  o1.y = fmaf(a.y, cki, b.y * ckr);
        o0.z = a.z * ckr - b.z * cki;  o1.z = fmaf(a.z, cki, b.z * ckr);
        o0.w = a.w * ckr - b.w * cki;  o1.w = fmaf(a.w, cki, b.w * ckr);
        __stcs(out + i, o0);
        __stcs(out + i + (size_t)W * (S / 4), o1);
    }
}

extern "C" void kernel_launch(void* const* d_in, const int* in_sizes, int n_in,
                              void* d_out, int out_size) {
    const float* holo_re = (const float*)d_in[0];
    const float* holo_im = (const float*)d_in[1];
    const float* cue_re  = (const float*)d_in[2];
    const float* cue_im  = (const float*)d_in[3];
    const float* keys_re = (const float*)d_in[4];
    const float* keys_im = (const float*)d_in[5];
    float* out = (float*)d_out;

    // k_mix: normal launch
    k_mix<<<W, 256>>>((const float4*)holo_re, (const float4*)holo_im,
                      (const float4*)cue_re, (const float4*)cue_im);

    // k_corr: PDL-dependent on k_mix
    {
        cudaLaunchConfig_t cfg = {};
        cfg.gridDim = dim3(NK, 1, 1);
        cfg.blockDim = dim3(256, 1, 1);
        cfg.dynamicSmemBytes = 0;
        cfg.stream = 0;
        cudaLaunchAttribute attr[1];
        attr[0].id = cudaLaunchAttributeProgrammaticStreamSerialization;
        attr[0].val.programmaticStreamSerializationAllowed = 1;
        cfg.attrs = attr;
        cfg.numAttrs = 1;
        cudaLaunchKernelEx(&cfg, k_corr,
                           (const float4*)keys_re, (const float4*)keys_im);
    }

    // k_out: PDL-dependent on k_corr
    {
        cudaLaunchConfig_t cfg = {};
        cfg.gridDim = dim3(W, 1, 1);
        cfg.blockDim = dim3(256, 1, 1);
        cfg.dynamicSmemBytes = 0;
        cfg.stream = 0;
        cudaLaunchAttribute attr[1];
        attr[0].id = cudaLaunchAttributeProgrammaticStreamSerialization;
        attr[0].val.programmaticStreamSerializationAllowed = 1;
        cfg.attrs = attr;
        cfg.numAttrs = 1;
        cudaLaunchKernelEx(&cfg, k_out,
                           (const float4*)holo_re, (const float4*)holo_im,
                           keys_re, keys_im, (float4*)out);
    }
}